// round 8
// baseline (speedup 1.0000x reference)
#include <cuda_runtime.h>

#define BQ 2
#define HQ 12
#define SQ 1024
#define DQ 64
#define KP 102            // max(1, int(1024 * 0.1))
#define ROWS (BQ * HQ * SQ)   // 24576 query rows

// Scratch (allocation-free contract): packed k sign bits, one u64 per key row.
__device__ unsigned long long g_kbits[ROWS];

// ---------------------------------------------------------------------------
// Kernel 1: pack sign bits of k rows into uint64 (warp per row).
// bit d of row r = (k[r][d] > 0). sign-dot = 64 - 2*popc(xor). Ranking by
// approx score desc == popcount asc; ties broken by lower index (JAX top_k).
// q bits are computed inside the attention kernel (it loads q anyway).
// ---------------------------------------------------------------------------
__global__ void pack_kernel(const float* __restrict__ k) {
    int warp = (blockIdx.x * blockDim.x + threadIdx.x) >> 5;
    int lane = threadIdx.x & 31;
    if (warp >= ROWS) return;
    const float* kr = k + (size_t)warp * DQ;
    unsigned klo = __ballot_sync(0xffffffffu, kr[lane] > 0.0f);
    unsigned khi = __ballot_sync(0xffffffffu, kr[lane + 32] > 0.0f);
    if (lane == 0)
        g_kbits[warp] = ((unsigned long long)khi << 32) | klo;
}

// ---------------------------------------------------------------------------
// Kernel 2: one CTA (256 threads) per query row.
//   Phase A: popcount vs all 1024 keys + histogram (65 bins)
//   Phase B: threshold bin c* + index-ordered rank within the tie bin
//   Phase C: precise scores for 102 selected keys (warp per 2 keys, float2)
//   Phase D: softmax (warp 0)
//   Phase E: weighted v accumulation (float2, 2-way unrolled over j)
// ---------------------------------------------------------------------------
__global__ __launch_bounds__(256) void attn_kernel(
    const float* __restrict__ q, const float* __restrict__ k,
    const float* __restrict__ v, const float* __restrict__ mask,
    float* __restrict__ out)
{
    int row = blockIdx.x;          // ((b*H + h) * S + s)
    int bh  = row >> 10;           // b*H + h
    int b   = bh / HQ;
    const unsigned long long* kb = g_kbits + (size_t)bh * SQ;
    const float* mrow = mask + (size_t)b * SQ;

    __shared__ unsigned char pc[SQ];
    __shared__ int   hist[65];
    __shared__ int   sel[KP];
    __shared__ __align__(8) float qs[DQ];   // 8B-aligned: read as float2 below
    __shared__ float score[KP];
    __shared__ unsigned flagw[32];
    __shared__ int   wordpre[32];
    __shared__ int   cstar_s, nless_s, remaining_s, cnt_s;
    __shared__ unsigned long long qbits_s;
    __shared__ float2 oacc[8][32];

    int tid  = threadIdx.x;
    int lane = tid & 31;
    int wid  = tid >> 5;

    if (tid < 65) hist[tid] = 0;
    if (tid < DQ) qs[tid] = q[(size_t)row * DQ + tid];
    if (tid == 0) cnt_s = 0;
    __syncthreads();

    // Derive q sign bits in-CTA (warp 0) from the q row already in smem.
    if (wid == 0) {
        unsigned qlo = __ballot_sync(0xffffffffu, qs[lane] > 0.0f);
        unsigned qhi = __ballot_sync(0xffffffffu, qs[lane + 32] > 0.0f);
        if (lane == 0)
            qbits_s = ((unsigned long long)qhi << 32) | qlo;
    }
    __syncthreads();
    unsigned long long qbits = qbits_s;

    // Phase A: popcounts + histogram
    #pragma unroll
    for (int c = 0; c < 4; c++) {
        int t = c * 256 + tid;
        int p = __popcll(qbits ^ kb[t]);
        pc[t] = (unsigned char)p;
        atomicAdd(&hist[p], 1);
    }
    __syncthreads();

    // Phase B1: find cutoff bin (bounded scan; hist sums to SQ >= KP)
    if (tid == 0) {
        int cum = 0, c = 0;
        while (c < 64 && cum + hist[c] < KP) { cum += hist[c]; c++; }
        cstar_s = c; nless_s = cum; remaining_s = KP - cum;
    }
    __syncthreads();
    int cstar = cstar_s, nless = nless_s, remaining = remaining_s;

    // Phase B2: packed flags (pc == c*) in key-index order
    #pragma unroll
    for (int c = 0; c < 4; c++) {
        int t = c * 256 + tid;
        unsigned bal = __ballot_sync(0xffffffffu, pc[t] == (unsigned char)cstar);
        if (lane == 0) flagw[c * 8 + wid] = bal;   // word (t>>5) = c*8 + wid
    }
    __syncthreads();
    if (tid == 0) {
        int acc = 0;
        #pragma unroll
        for (int w = 0; w < 32; w++) { wordpre[w] = acc; acc += __popc(flagw[w]); }
    }
    __syncthreads();

    // Phase B3: emit selected indices. pc<c*: any slot. pc==c*: first
    // `remaining` in index order (matches JAX lower-index-first tie break).
    #pragma unroll
    for (int c = 0; c < 4; c++) {
        int t = c * 256 + tid;
        int p = pc[t];
        if (p < cstar) {
            int slot = atomicAdd(&cnt_s, 1);
            sel[slot] = t;
        } else if (p == cstar) {
            int w = t >> 5;
            int rank = wordpre[w] + __popc(flagw[w] & ((1u << lane) - 1u));
            if (rank < remaining) sel[nless + rank] = t;
        }
    }
    __syncthreads();

    // Phase C: precise scores. Warp handles keys j and j+8 per iteration:
    // two independent gathered LDG.64s in flight before the shfl reductions.
    const float* kbase = k + (size_t)bh * SQ * DQ;
    float2 q2 = reinterpret_cast<const float2*>(qs)[lane];  // aligned smem read
    for (int j = wid; j < KP; j += 16) {
        int  j1   = j + 8;
        bool has1 = (j1 < KP);
        int idx0 = sel[j];
        int idx1 = has1 ? sel[j1] : idx0;
        float2 k20 = reinterpret_cast<const float2*>(kbase + (size_t)idx0 * DQ)[lane];
        float2 k21 = reinterpret_cast<const float2*>(kbase + (size_t)idx1 * DQ)[lane];
        float p0 = q2.x * k20.x + q2.y * k20.y;
        float p1 = q2.x * k21.x + q2.y * k21.y;
        #pragma unroll
        for (int o = 16; o; o >>= 1) {
            p0 += __shfl_xor_sync(0xffffffffu, p0, o);
            p1 += __shfl_xor_sync(0xffffffffu, p1, o);
        }
        if (lane == 0) {
            score[j] = p0 * 0.125f + mrow[idx0];
            if (has1) score[j1] = p1 * 0.125f + mrow[idx1];
        }
    }
    __syncthreads();

    // Phase D: softmax over 102 (warp 0)
    if (wid == 0) {
        float m = -1e30f;
        #pragma unroll
        for (int c = 0; c < 4; c++) {
            int j = c * 32 + lane;
            if (j < KP) m = fmaxf(m, score[j]);
        }
        #pragma unroll
        for (int o = 16; o; o >>= 1)
            m = fmaxf(m, __shfl_xor_sync(0xffffffffu, m, o));
        float s = 0.0f;
        float e[4];
        #pragma unroll
        for (int c = 0; c < 4; c++) {
            int j = c * 32 + lane;
            e[c] = (j < KP) ? __expf(score[j] - m) : 0.0f;
            s += e[c];
        }
        #pragma unroll
        for (int o = 16; o; o >>= 1)
            s += __shfl_xor_sync(0xffffffffu, s, o);
        float inv = 1.0f / s;
        #pragma unroll
        for (int c = 0; c < 4; c++) {
            int j = c * 32 + lane;
            if (j < KP) score[j] = e[c] * inv;
        }
    }
    __syncthreads();

    // Phase E: out[d] = sum_j p_j * v[sel_j][d]; float2 per lane,
    // 8 j-groups, 2 keys in flight per iteration.
    const float* vbase = v + (size_t)bh * SQ * DQ;
    float2 acc = make_float2(0.0f, 0.0f);
    for (int j = wid; j < KP; j += 16) {
        int  j1   = j + 8;
        bool has1 = (j1 < KP);
        float p0 = score[j];
        float p1 = has1 ? score[j1] : 0.0f;
        int idx0 = sel[j];
        int idx1 = has1 ? sel[j1] : idx0;
        float2 v0 = reinterpret_cast<const float2*>(vbase + (size_t)idx0 * DQ)[lane];
        float2 v1 = reinterpret_cast<const float2*>(vbase + (size_t)idx1 * DQ)[lane];
        acc.x += p0 * v0.x + p1 * v1.x;
        acc.y += p0 * v0.y + p1 * v1.y;
    }
    oacc[wid][lane] = acc;
    __syncthreads();
    if (tid < 32) {
        float2 r = oacc[0][tid];
        #pragma unroll
        for (int g = 1; g < 8; g++) {
            float2 t = oacc[g][tid];
            r.x += t.x; r.y += t.y;
        }
        reinterpret_cast<float2*>(out + (size_t)row * DQ)[tid] = r;
    }
}

extern "C" void kernel_launch(void* const* d_in, const int* in_sizes, int n_in,
                              void* d_out, int out_size) {
    const float* q    = (const float*)d_in[0];
    const float* k    = (const float*)d_in[1];
    const float* v    = (const float*)d_in[2];
    const float* mask = (const float*)d_in[3];
    float* out = (float*)d_out;

    pack_kernel<<<ROWS / 8, 256>>>(k);          // 8 warps/block, 3072 blocks
    attn_kernel<<<ROWS, 256>>>(q, k, v, mask, out);
}

// round 11
// speedup vs baseline: 1.1327x; 1.1327x over previous
#include <cuda_runtime.h>

#define BQ 2
#define HQ 12
#define SQ 1024
#define DQ 64
#define KP 102            // max(1, int(1024 * 0.1))
#define ROWS (BQ * HQ * SQ)   // 24576 query rows

// Scratch (allocation-free contract): packed k sign bits, one u64 per key row.
__device__ unsigned long long g_kbits[ROWS];

// ---------------------------------------------------------------------------
// Kernel 1: pack sign bits of k rows into uint64 (warp per row).
// sign-dot = 64 - 2*popc(xor); score desc == popcount asc; ties -> lower idx.
// ---------------------------------------------------------------------------
__global__ void pack_kernel(const float* __restrict__ k) {
    int warp = (blockIdx.x * blockDim.x + threadIdx.x) >> 5;
    int lane = threadIdx.x & 31;
    if (warp >= ROWS) return;
    const float* kr = k + (size_t)warp * DQ;
    unsigned klo = __ballot_sync(0xffffffffu, kr[lane] > 0.0f);
    unsigned khi = __ballot_sync(0xffffffffu, kr[lane + 32] > 0.0f);
    if (lane == 0)
        g_kbits[warp] = ((unsigned long long)khi << 32) | klo;
}

// ---------------------------------------------------------------------------
// Kernel 2: one CTA (256 threads) per query row.
//   A: popcounts (registers) + match-aggregated per-warp histograms
//   B: cutoff bin + index-ordered rank for the tie bin (register flags)
//   C: precise scores, half-warp (16 lanes) per key, float4 loads, MLP=2
//   D: softmax (warp 0)
//   E: weighted v accumulation, half-warp per key, float4, MLP=2
// ---------------------------------------------------------------------------
__global__ __launch_bounds__(256) void attn_kernel(
    const float* __restrict__ q, const float* __restrict__ k,
    const float* __restrict__ v, const float* __restrict__ mask,
    float* __restrict__ out)
{
    int row = blockIdx.x;          // ((b*H + h) * S + s)
    int bh  = row >> 10;           // b*H + h
    int b   = bh / HQ;
    const unsigned long long* kb = g_kbits + (size_t)bh * SQ;
    const float* mrow = mask + (size_t)b * SQ;

    __shared__ int   histw[8][65];          // per-warp histogram slices
    __shared__ int   hist[65];
    __shared__ int   sel[KP];
    __shared__ __align__(16) float qs[DQ];
    __shared__ float score[KP];
    __shared__ float smask[SQ];             // mask row, coalesced preload
    __shared__ unsigned flagw[32];
    __shared__ int   wordpre[32];
    __shared__ int   cstar_s, nless_s, remaining_s, cnt_s;
    __shared__ unsigned long long qbits_s;
    __shared__ __align__(16) float4 oacc[16][16];  // [slot][hl]

    int tid  = threadIdx.x;
    int lane = tid & 31;
    int wid  = tid >> 5;
    int half = lane >> 4;          // 0 or 1: which key of the warp's pair
    int hl   = lane & 15;          // lane within the 16-lane half

    // init + coalesced preloads
    for (int i = tid; i < 8 * 65; i += 256) ((int*)histw)[i] = 0;
    if (tid < DQ) qs[tid] = q[(size_t)row * DQ + tid];
    #pragma unroll
    for (int c = 0; c < 4; c++) smask[c * 256 + tid] = mrow[c * 256 + tid];
    if (tid == 0) cnt_s = 0;
    __syncthreads();

    // q sign bits in-CTA (warp 0)
    if (wid == 0) {
        unsigned qlo = __ballot_sync(0xffffffffu, qs[lane] > 0.0f);
        unsigned qhi = __ballot_sync(0xffffffffu, qs[lane + 32] > 0.0f);
        if (lane == 0)
            qbits_s = ((unsigned long long)qhi << 32) | qlo;
    }
    __syncthreads();
    unsigned long long qbits = qbits_s;

    // Phase A: popcounts in registers; match-aggregated per-warp histogram
    int p[4];
    #pragma unroll
    for (int c = 0; c < 4; c++) {
        int t = c * 256 + tid;
        p[c] = __popcll(qbits ^ kb[t]);
        unsigned mm = __match_any_sync(0xffffffffu, p[c]);
        if ((mm & ((1u << lane) - 1u)) == 0)     // lowest lane of match group
            atomicAdd(&histw[wid][p[c]], __popc(mm));
    }
    __syncthreads();

    // reduce per-warp slices
    if (tid < 65) {
        int s = 0;
        #pragma unroll
        for (int w = 0; w < 8; w++) s += histw[w][tid];
        hist[tid] = s;
    }
    __syncthreads();

    // Phase B1: find cutoff bin (bounded scan)
    if (tid == 0) {
        int cum = 0, c = 0;
        while (c < 64 && cum + hist[c] < KP) { cum += hist[c]; c++; }
        cstar_s = c; nless_s = cum; remaining_s = KP - cum;
    }
    __syncthreads();
    int cstar = cstar_s, nless = nless_s, remaining = remaining_s;

    // Phase B2: packed tie flags in key-index order (from registers)
    #pragma unroll
    for (int c = 0; c < 4; c++) {
        unsigned bal = __ballot_sync(0xffffffffu, p[c] == cstar);
        if (lane == 0) flagw[c * 8 + wid] = bal;   // word (t>>5) = c*8+wid
    }
    __syncthreads();
    if (tid == 0) {
        int acc = 0;
        #pragma unroll
        for (int w = 0; w < 32; w++) { wordpre[w] = acc; acc += __popc(flagw[w]); }
    }
    __syncthreads();

    // Phase B3: emit selected indices (JAX lower-index tie break)
    #pragma unroll
    for (int c = 0; c < 4; c++) {
        int t = c * 256 + tid;
        if (p[c] < cstar) {
            int slot = atomicAdd(&cnt_s, 1);
            sel[slot] = t;
        } else if (p[c] == cstar) {
            int w = t >> 5;
            int rank = wordpre[w] + __popc(flagw[w] & ((1u << lane) - 1u));
            if (rank < remaining) sel[nless + rank] = t;
        }
    }
    __syncthreads();

    // Phase C: precise scores. Each half-warp owns one key; warp covers keys
    // jj and jj+16 per unrolled iteration (2 LDG.128 in flight).
    const float* kbase = k + (size_t)bh * SQ * DQ;
    float4 q4 = reinterpret_cast<const float4*>(qs)[hl];
    int jj = 2 * wid + half;
    for (; jj + 16 < KP; jj += 32) {
        int i0 = sel[jj], i1 = sel[jj + 16];
        float4 ka = reinterpret_cast<const float4*>(kbase + (size_t)i0 * DQ)[hl];
        float4 kc = reinterpret_cast<const float4*>(kbase + (size_t)i1 * DQ)[hl];
        float p0 = q4.x * ka.x + q4.y * ka.y + q4.z * ka.z + q4.w * ka.w;
        float p1 = q4.x * kc.x + q4.y * kc.y + q4.z * kc.z + q4.w * kc.w;
        #pragma unroll
        for (int o = 8; o; o >>= 1) {
            p0 += __shfl_xor_sync(0xffffffffu, p0, o);
            p1 += __shfl_xor_sync(0xffffffffu, p1, o);
        }
        if (hl == 0) {
            score[jj]      = p0 * 0.125f + smask[i0];
            score[jj + 16] = p1 * 0.125f + smask[i1];
        }
    }
    for (; jj < KP; jj += 16) {
        int i0 = sel[jj];
        float4 ka = reinterpret_cast<const float4*>(kbase + (size_t)i0 * DQ)[hl];
        float p0 = q4.x * ka.x + q4.y * ka.y + q4.z * ka.z + q4.w * ka.w;
        #pragma unroll
        for (int o = 8; o; o >>= 1)
            p0 += __shfl_xor_sync(0xffffffffu, p0, o);
        if (hl == 0)
            score[jj] = p0 * 0.125f + smask[i0];
    }
    __syncthreads();

    // Phase D: softmax over 102 (warp 0)
    if (wid == 0) {
        float m = -1e30f;
        #pragma unroll
        for (int c = 0; c < 4; c++) {
            int j = c * 32 + lane;
            if (j < KP) m = fmaxf(m, score[j]);
        }
        #pragma unroll
        for (int o = 16; o; o >>= 1)
            m = fmaxf(m, __shfl_xor_sync(0xffffffffu, m, o));
        float s = 0.0f;
        float e[4];
        #pragma unroll
        for (int c = 0; c < 4; c++) {
            int j = c * 32 + lane;
            e[c] = (j < KP) ? __expf(score[j] - m) : 0.0f;
            s += e[c];
        }
        #pragma unroll
        for (int o = 16; o; o >>= 1)
            s += __shfl_xor_sync(0xffffffffu, s, o);
        float inv = 1.0f / s;
        #pragma unroll
        for (int c = 0; c < 4; c++) {
            int j = c * 32 + lane;
            if (j < KP) score[j] = e[c] * inv;
        }
    }
    __syncthreads();

    // Phase E: out[d] = sum_j p_j * v[sel_j][d]; half-warp per key, float4.
    const float* vbase = v + (size_t)bh * SQ * DQ;
    float4 acc = make_float4(0.0f, 0.0f, 0.0f, 0.0f);
    jj = 2 * wid + half;
    for (; jj + 16 < KP; jj += 32) {
        float p0 = score[jj], p1 = score[jj + 16];
        float4 va = reinterpret_cast<const float4*>(vbase + (size_t)sel[jj] * DQ)[hl];
        float4 vb = reinterpret_cast<const float4*>(vbase + (size_t)sel[jj + 16] * DQ)[hl];
        acc.x += p0 * va.x + p1 * vb.x;
        acc.y += p0 * va.y + p1 * vb.y;
        acc.z += p0 * va.z + p1 * vb.z;
        acc.w += p0 * va.w + p1 * vb.w;
    }
    for (; jj < KP; jj += 16) {
        float p0 = score[jj];
        float4 va = reinterpret_cast<const float4*>(vbase + (size_t)sel[jj] * DQ)[hl];
        acc.x += p0 * va.x;
        acc.y += p0 * va.y;
        acc.z += p0 * va.z;
        acc.w += p0 * va.w;
    }
    oacc[wid * 2 + half][hl] = acc;
    __syncthreads();
    if (tid < DQ) {
        const float* of = reinterpret_cast<const float*>(oacc);  // [16][64]
        float r = 0.0f;
        #pragma unroll
        for (int s = 0; s < 16; s++) r += of[s * 64 + tid];
        out[(size_t)row * DQ + tid] = r;
    }
}

extern "C" void kernel_launch(void* const* d_in, const int* in_sizes, int n_in,
                              void* d_out, int out_size) {
    const float* q    = (const float*)d_in[0];
    const float* k    = (const float*)d_in[1];
    const float* v    = (const float*)d_in[2];
    const float* mask = (const float*)d_in[3];
    float* out = (float*)d_out;

    pack_kernel<<<ROWS / 8, 256>>>(k);          // 8 warps/block, 3072 blocks
    attn_kernel<<<ROWS, 256>>>(q, k, v, mask, out);
}

// round 12
// speedup vs baseline: 1.1484x; 1.0138x over previous
#include <cuda_runtime.h>

#define BQ 2
#define HQ 12
#define SQ 1024
#define DQ 64
#define KP 102            // max(1, int(1024 * 0.1))
#define ROWS (BQ * HQ * SQ)   // 24576 query rows

// Scratch (allocation-free contract): packed k sign bits, one u64 per key row.
__device__ unsigned long long g_kbits[ROWS];

// ---------------------------------------------------------------------------
// Kernel 1: pack sign bits of k rows into uint64 (warp per row).
// sign-dot = 64 - 2*popc(xor); score desc == popcount asc; ties -> lower idx.
// ---------------------------------------------------------------------------
__global__ void pack_kernel(const float* __restrict__ k) {
    int warp = (blockIdx.x * blockDim.x + threadIdx.x) >> 5;
    int lane = threadIdx.x & 31;
    if (warp >= ROWS) return;
    const float* kr = k + (size_t)warp * DQ;
    unsigned klo = __ballot_sync(0xffffffffu, kr[lane] > 0.0f);
    unsigned khi = __ballot_sync(0xffffffffu, kr[lane + 32] > 0.0f);
    if (lane == 0)
        g_kbits[warp] = ((unsigned long long)khi << 32) | klo;
}

// ---------------------------------------------------------------------------
// Kernel 2: one CTA (256 threads) per query row. Fully atomic-free.
//   A: popcounts (registers, MLP-4) + match-aggregated NON-ATOMIC per-warp hist
//   B: cutoff bin; dual ballots (lt/eq) + warp-0 shfl prefix; ordered emit
//   C: precise scores, half-warp per key, float4 loads, MLP=2
//   D: softmax (warp 0)
//   E: weighted v accumulation, half-warp per key, float4, MLP=2
// ---------------------------------------------------------------------------
__global__ __launch_bounds__(256) void attn_kernel(
    const float* __restrict__ q, const float* __restrict__ k,
    const float* __restrict__ v, const float* __restrict__ mask,
    float* __restrict__ out)
{
    int row = blockIdx.x;          // ((b*H + h) * S + s)
    int bh  = row >> 10;           // b*H + h
    int b   = bh / HQ;
    const unsigned long long* kb = g_kbits + (size_t)bh * SQ;
    const float* mrow = mask + (size_t)b * SQ;

    __shared__ int   histw[8][65];          // per-warp histogram slices
    __shared__ int   hist[65];
    __shared__ int   sel[KP];
    __shared__ __align__(16) float qs[DQ];
    __shared__ float score[KP];
    __shared__ float smask[SQ];             // mask row, coalesced preload
    __shared__ unsigned flagl[32], flage[32];
    __shared__ int   prel[32], pree[32];
    __shared__ int   cstar_s, nless_s, remaining_s;
    __shared__ unsigned long long qbits_s;
    __shared__ __align__(16) float4 oacc[16][16];  // [slot][hl]

    int tid  = threadIdx.x;
    int lane = tid & 31;
    int wid  = tid >> 5;
    int half = lane >> 4;          // 0 or 1: which key of the warp's pair
    int hl   = lane & 15;          // lane within the 16-lane half

    // init + coalesced preloads
    for (int i = tid; i < 8 * 65; i += 256) ((int*)histw)[i] = 0;
    if (tid < DQ) qs[tid] = q[(size_t)row * DQ + tid];
    #pragma unroll
    for (int c = 0; c < 4; c++) smask[c * 256 + tid] = mrow[c * 256 + tid];
    __syncthreads();

    // q sign bits in-CTA (warp 0)
    if (wid == 0) {
        unsigned qlo = __ballot_sync(0xffffffffu, qs[lane] > 0.0f);
        unsigned qhi = __ballot_sync(0xffffffffu, qs[lane + 32] > 0.0f);
        if (lane == 0)
            qbits_s = ((unsigned long long)qhi << 32) | qlo;
    }
    __syncthreads();
    unsigned long long qbits = qbits_s;

    // Phase A: popcounts (4 loads in flight), then non-atomic per-warp hist.
    int p[4];
    #pragma unroll
    for (int c = 0; c < 4; c++)
        p[c] = __popcll(qbits ^ kb[c * 256 + tid]);
    #pragma unroll
    for (int c = 0; c < 4; c++) {
        unsigned mm = __match_any_sync(0xffffffffu, p[c]);
        // group leaders hit distinct addresses within this warp's slice
        if ((mm & ((1u << lane) - 1u)) == 0)
            histw[wid][p[c]] += __popc(mm);
        __syncwarp();  // order iteration c's STS before c+1's LDS
    }
    __syncthreads();

    // reduce per-warp slices
    if (tid < 65) {
        int s = 0;
        #pragma unroll
        for (int w = 0; w < 8; w++) s += histw[w][tid];
        hist[tid] = s;
    }
    __syncthreads();

    // Phase B1: cutoff bin (bounded scan)
    if (tid == 0) {
        int cum = 0, c = 0;
        while (c < 64 && cum + hist[c] < KP) { cum += hist[c]; c++; }
        cstar_s = c; nless_s = cum; remaining_s = KP - cum;
    }
    __syncthreads();
    int cstar = cstar_s, nless = nless_s, remaining = remaining_s;

    // Phase B2: dual packed flags (lt / eq) in key-index order
    #pragma unroll
    for (int c = 0; c < 4; c++) {
        unsigned blt = __ballot_sync(0xffffffffu, p[c] <  cstar);
        unsigned beq = __ballot_sync(0xffffffffu, p[c] == cstar);
        if (lane == 0) { flagl[c * 8 + wid] = blt; flage[c * 8 + wid] = beq; }
    }
    __syncthreads();
    // warp 0: exclusive prefix over the 32 words for both flag sets
    if (wid == 0) {
        int cl = __popc(flagl[lane]);
        int ce = __popc(flage[lane]);
        int sl = cl, se = ce;
        #pragma unroll
        for (int o = 1; o < 32; o <<= 1) {
            int tl = __shfl_up_sync(0xffffffffu, sl, o);
            int te = __shfl_up_sync(0xffffffffu, se, o);
            if (lane >= o) { sl += tl; se += te; }
        }
        prel[lane] = sl - cl;
        pree[lane] = se - ce;
    }
    __syncthreads();

    // Phase B3: atomic-free emit (JAX lower-index tie break for the eq bin)
    #pragma unroll
    for (int c = 0; c < 4; c++) {
        int t = c * 256 + tid;
        int w = t >> 5;
        if (p[c] < cstar) {
            int slot = prel[w] + __popc(flagl[w] & ((1u << lane) - 1u));
            sel[slot] = t;
        } else if (p[c] == cstar) {
            int rank = pree[w] + __popc(flage[w] & ((1u << lane) - 1u));
            if (rank < remaining) sel[nless + rank] = t;
        }
    }
    __syncthreads();

    // Phase C: precise scores. Each half-warp owns one key; warp covers keys
    // jj and jj+16 per unrolled iteration (2 LDG.128 in flight).
    const float* kbase = k + (size_t)bh * SQ * DQ;
    float4 q4 = reinterpret_cast<const float4*>(qs)[hl];
    int jj = 2 * wid + half;
    for (; jj + 16 < KP; jj += 32) {
        int i0 = sel[jj], i1 = sel[jj + 16];
        float4 ka = reinterpret_cast<const float4*>(kbase + (size_t)i0 * DQ)[hl];
        float4 kc = reinterpret_cast<const float4*>(kbase + (size_t)i1 * DQ)[hl];
        float p0 = q4.x * ka.x + q4.y * ka.y + q4.z * ka.z + q4.w * ka.w;
        float p1 = q4.x * kc.x + q4.y * kc.y + q4.z * kc.z + q4.w * kc.w;
        #pragma unroll
        for (int o = 8; o; o >>= 1) {
            p0 += __shfl_xor_sync(0xffffffffu, p0, o);
            p1 += __shfl_xor_sync(0xffffffffu, p1, o);
        }
        if (hl == 0) {
            score[jj]      = p0 * 0.125f + smask[i0];
            score[jj + 16] = p1 * 0.125f + smask[i1];
        }
    }
    for (; jj < KP; jj += 16) {
        int i0 = sel[jj];
        float4 ka = reinterpret_cast<const float4*>(kbase + (size_t)i0 * DQ)[hl];
        float p0 = q4.x * ka.x + q4.y * ka.y + q4.z * ka.z + q4.w * ka.w;
        #pragma unroll
        for (int o = 8; o; o >>= 1)
            p0 += __shfl_xor_sync(0xffffffffu, p0, o);
        if (hl == 0)
            score[jj] = p0 * 0.125f + smask[i0];
    }
    __syncthreads();

    // Phase D: softmax over 102 (warp 0)
    if (wid == 0) {
        float m = -1e30f;
        #pragma unroll
        for (int c = 0; c < 4; c++) {
            int j = c * 32 + lane;
            if (j < KP) m = fmaxf(m, score[j]);
        }
        #pragma unroll
        for (int o = 16; o; o >>= 1)
            m = fmaxf(m, __shfl_xor_sync(0xffffffffu, m, o));
        float s = 0.0f;
        float e[4];
        #pragma unroll
        for (int c = 0; c < 4; c++) {
            int j = c * 32 + lane;
            e[c] = (j < KP) ? __expf(score[j] - m) : 0.0f;
            s += e[c];
        }
        #pragma unroll
        for (int o = 16; o; o >>= 1)
            s += __shfl_xor_sync(0xffffffffu, s, o);
        float inv = 1.0f / s;
        #pragma unroll
        for (int c = 0; c < 4; c++) {
            int j = c * 32 + lane;
            if (j < KP) score[j] = e[c] * inv;
        }
    }
    __syncthreads();

    // Phase E: out[d] = sum_j p_j * v[sel_j][d]; half-warp per key, float4.
    const float* vbase = v + (size_t)bh * SQ * DQ;
    float4 acc = make_float4(0.0f, 0.0f, 0.0f, 0.0f);
    jj = 2 * wid + half;
    for (; jj + 16 < KP; jj += 32) {
        float p0 = score[jj], p1 = score[jj + 16];
        float4 va = reinterpret_cast<const float4*>(vbase + (size_t)sel[jj] * DQ)[hl];
        float4 vb = reinterpret_cast<const float4*>(vbase + (size_t)sel[jj + 16] * DQ)[hl];
        acc.x += p0 * va.x + p1 * vb.x;
        acc.y += p0 * va.y + p1 * vb.y;
        acc.z += p0 * va.z + p1 * vb.z;
        acc.w += p0 * va.w + p1 * vb.w;
    }
    for (; jj < KP; jj += 16) {
        float p0 = score[jj];
        float4 va = reinterpret_cast<const float4*>(vbase + (size_t)sel[jj] * DQ)[hl];
        acc.x += p0 * va.x;
        acc.y += p0 * va.y;
        acc.z += p0 * va.z;
        acc.w += p0 * va.w;
    }
    oacc[wid * 2 + half][hl] = acc;
    __syncthreads();
    if (tid < DQ) {
        const float* of = reinterpret_cast<const float*>(oacc);  // [16][64]
        float r = 0.0f;
        #pragma unroll
        for (int s = 0; s < 16; s++) r += of[s * 64 + tid];
        out[(size_t)row * DQ + tid] = r;
    }
}

extern "C" void kernel_launch(void* const* d_in, const int* in_sizes, int n_in,
                              void* d_out, int out_size) {
    const float* q    = (const float*)d_in[0];
    const float* k    = (const float*)d_in[1];
    const float* v    = (const float*)d_in[2];
    const float* mask = (const float*)d_in[3];
    float* out = (float*)d_out;

    pack_kernel<<<ROWS / 8, 256>>>(k);          // 8 warps/block, 3072 blocks
    attn_kernel<<<ROWS, 256>>>(q, k, v, mask, out);
}

// round 14
// speedup vs baseline: 1.1897x; 1.0360x over previous
#include <cuda_runtime.h>

#define BQ 2
#define HQ 12
#define SQ 1024
#define DQ 64
#define KP 102            // max(1, int(1024 * 0.1))
#define ROWS (BQ * HQ * SQ)   // 24576 query rows

// Scratch (allocation-free contract): packed k sign bits, one u64 per key row.
__device__ unsigned long long g_kbits[ROWS];

// ---------------------------------------------------------------------------
// Kernel 1: pack sign bits of k rows into uint64 (warp per row).
// sign-dot = 64 - 2*popc(xor); score desc == popcount asc; ties -> lower idx.
// ---------------------------------------------------------------------------
__global__ void pack_kernel(const float* __restrict__ k) {
    int warp = (blockIdx.x * blockDim.x + threadIdx.x) >> 5;
    int lane = threadIdx.x & 31;
    if (warp >= ROWS) return;
    const float* kr = k + (size_t)warp * DQ;
    unsigned klo = __ballot_sync(0xffffffffu, kr[lane] > 0.0f);
    unsigned khi = __ballot_sync(0xffffffffu, kr[lane + 32] > 0.0f);
    if (lane == 0)
        g_kbits[warp] = ((unsigned long long)khi << 32) | klo;
}

// ---------------------------------------------------------------------------
// Kernel 2: one CTA (256 threads) per query row. Atomic-free, 8 barriers.
//   A: popcounts (registers, MLP-4) + match-aggregated per-warp hist (smem)
//   B1: warp-0 parallel reduce+scan+ballot cutoff (~100 cy, was ~1250 serial)
//   B2/B3: dual ballots; every warp redundantly scans word prefixes (no bar)
//   C: precise scores, half-warp per key, float4, MLP=2
//   D: softmax (warp 0)
//   E: weighted v accumulation, half-warp per key, float4, MLP=2
// ---------------------------------------------------------------------------
__global__ __launch_bounds__(256) void attn_kernel(
    const float* __restrict__ q, const float* __restrict__ k,
    const float* __restrict__ v, const float* __restrict__ mask,
    float* __restrict__ out)
{
    int row = blockIdx.x;          // ((b*H + h) * S + s)
    int bh  = row >> 10;           // b*H + h
    int b   = bh / HQ;
    const unsigned long long* kb = g_kbits + (size_t)bh * SQ;
    const float* mrow = mask + (size_t)b * SQ;

    __shared__ int   histw[8][65];          // per-warp histogram slices
    __shared__ int   sel[KP];
    __shared__ __align__(16) float qs[DQ];
    __shared__ float score[KP];
    __shared__ float smask[SQ];             // mask row, coalesced preload
    __shared__ unsigned flagl[32], flage[32];
    __shared__ int   cstar_s, nless_s, remaining_s;
    __shared__ __align__(16) float4 oacc[16][16];  // [slot][hl]

    int tid  = threadIdx.x;
    int lane = tid & 31;
    int wid  = tid >> 5;
    int half = lane >> 4;          // 0 or 1: which key of the warp's pair
    int hl   = lane & 15;          // lane within the 16-lane half

    // init + coalesced preloads
    for (int i = tid; i < 8 * 65; i += 256) ((int*)histw)[i] = 0;
    if (tid < DQ) qs[tid] = q[(size_t)row * DQ + tid];
    #pragma unroll
    for (int c = 0; c < 4; c++) smask[c * 256 + tid] = mrow[c * 256 + tid];
    __syncthreads();                                              // bar 1

    // q sign bits: every warp computes redundantly from smem (no barrier)
    unsigned qlo = __ballot_sync(0xffffffffu, qs[lane] > 0.0f);
    unsigned qhi = __ballot_sync(0xffffffffu, qs[lane + 32] > 0.0f);
    unsigned long long qbits = ((unsigned long long)qhi << 32) | qlo;

    // Phase A: popcounts (4 loads in flight), non-atomic per-warp hist.
    int p[4];
    #pragma unroll
    for (int c = 0; c < 4; c++)
        p[c] = __popcll(qbits ^ kb[c * 256 + tid]);
    #pragma unroll
    for (int c = 0; c < 4; c++) {
        unsigned mm = __match_any_sync(0xffffffffu, p[c]);
        if ((mm & ((1u << lane) - 1u)) == 0)     // lowest lane of match group
            histw[wid][p[c]] += __popc(mm);
        __syncwarp();  // order iteration c's STS before c+1's LDS
    }
    __syncthreads();                                              // bar 2

    // Phase B1: warp 0 fused reduce + inclusive scan + cutoff (bins 2l,2l+1)
    if (wid == 0) {
        int x0 = 0, x1 = 0;
        #pragma unroll
        for (int w = 0; w < 8; w++) {
            x0 += histw[w][2 * lane];
            x1 += histw[w][2 * lane + 1];
        }
        int pair = x0 + x1;
        int incl = pair;
        #pragma unroll
        for (int o = 1; o < 32; o <<= 1) {
            int t = __shfl_up_sync(0xffffffffu, incl, o);
            if (lane >= o) incl += t;
        }
        int excl = incl - pair;          // cum before bin 2*lane
        unsigned bal = __ballot_sync(0xffffffffu, incl >= KP);
        if (bal) {
            int lstar = __ffs(bal) - 1;
            if (lane == lstar) {
                int cst, nls;
                if (excl + x0 >= KP) { cst = 2 * lane;     nls = excl; }
                else                 { cst = 2 * lane + 1; nls = excl + x0; }
                cstar_s = cst; nless_s = nls; remaining_s = KP - nls;
            }
        } else if (lane == 31) {         // pathological: cutoff in bin 64
            cstar_s = 64; nless_s = incl; remaining_s = KP - incl;
        }
    }
    __syncthreads();                                              // bar 3
    int cstar = cstar_s, nless = nless_s, remaining = remaining_s;

    // Phase B2: dual packed flags (lt / eq) in key-index order
    #pragma unroll
    for (int c = 0; c < 4; c++) {
        unsigned blt = __ballot_sync(0xffffffffu, p[c] <  cstar);
        unsigned beq = __ballot_sync(0xffffffffu, p[c] == cstar);
        if (lane == 0) { flagl[c * 8 + wid] = blt; flage[c * 8 + wid] = beq; }
    }
    __syncthreads();                                              // bar 4

    // Every warp redundantly scans the 32 flag words (identical results).
    int cl = __popc(flagl[lane]);
    int ce = __popc(flage[lane]);
    int sl = cl, se = ce;
    #pragma unroll
    for (int o = 1; o < 32; o <<= 1) {
        int tl = __shfl_up_sync(0xffffffffu, sl, o);
        int te = __shfl_up_sync(0xffffffffu, se, o);
        if (lane >= o) { sl += tl; se += te; }
    }
    int el = sl - cl, ee = se - ce;      // exclusive prefix of word `lane`

    // Phase B3: atomic-free emit (JAX lower-index tie break for the eq bin)
    #pragma unroll
    for (int c = 0; c < 4; c++) {
        int t = c * 256 + tid;
        int w = c * 8 + wid;
        int basel = __shfl_sync(0xffffffffu, el, w);
        int basee = __shfl_sync(0xffffffffu, ee, w);
        if (p[c] < cstar) {
            sel[basel + __popc(flagl[w] & ((1u << lane) - 1u))] = t;
        } else if (p[c] == cstar) {
            int rank = basee + __popc(flage[w] & ((1u << lane) - 1u));
            if (rank < remaining) sel[nless + rank] = t;
        }
    }
    __syncthreads();                                              // bar 5

    // Phase C: precise scores. Each half-warp owns one key; warp covers keys
    // jj and jj+16 per unrolled iteration (2 LDG.128 in flight).
    const float* kbase = k + (size_t)bh * SQ * DQ;
    float4 q4 = reinterpret_cast<const float4*>(qs)[hl];
    int jj = 2 * wid + half;
    for (; jj + 16 < KP; jj += 32) {
        int i0 = sel[jj], i1 = sel[jj + 16];
        float4 ka = reinterpret_cast<const float4*>(kbase + (size_t)i0 * DQ)[hl];
        float4 kc = reinterpret_cast<const float4*>(kbase + (size_t)i1 * DQ)[hl];
        float p0 = q4.x * ka.x + q4.y * ka.y + q4.z * ka.z + q4.w * ka.w;
        float p1 = q4.x * kc.x + q4.y * kc.y + q4.z * kc.z + q4.w * kc.w;
        #pragma unroll
        for (int o = 8; o; o >>= 1) {
            p0 += __shfl_xor_sync(0xffffffffu, p0, o);
            p1 += __shfl_xor_sync(0xffffffffu, p1, o);
        }
        if (hl == 0) {
            score[jj]      = p0 * 0.125f + smask[i0];
            score[jj + 16] = p1 * 0.125f + smask[i1];
        }
    }
    for (; jj < KP; jj += 16) {
        int i0 = sel[jj];
        float4 ka = reinterpret_cast<const float4*>(kbase + (size_t)i0 * DQ)[hl];
        float p0 = q4.x * ka.x + q4.y * ka.y + q4.z * ka.z + q4.w * ka.w;
        #pragma unroll
        for (int o = 8; o; o >>= 1)
            p0 += __shfl_xor_sync(0xffffffffu, p0, o);
        if (hl == 0)
            score[jj] = p0 * 0.125f + smask[i0];
    }
    __syncthreads();                                              // bar 6

    // Phase D: softmax over 102 (warp 0)
    if (wid == 0) {
        float m = -1e30f;
        #pragma unroll
        for (int c = 0; c < 4; c++) {
            int j = c * 32 + lane;
            if (j < KP) m = fmaxf(m, score[j]);
        }
        #pragma unroll
        for (int o = 16; o; o >>= 1)
            m = fmaxf(m, __shfl_xor_sync(0xffffffffu, m, o));
        float s = 0.0f;
        float e[4];
        #pragma unroll
        for (int c = 0; c < 4; c++) {
            int j = c * 32 + lane;
            e[c] = (j < KP) ? __expf(score[j] - m) : 0.0f;
            s += e[c];
        }
        #pragma unroll
        for (int o = 16; o; o >>= 1)
            s += __shfl_xor_sync(0xffffffffu, s, o);
        float inv = 1.0f / s;
        #pragma unroll
        for (int c = 0; c < 4; c++) {
            int j = c * 32 + lane;
            if (j < KP) score[j] = e[c] * inv;
        }
    }
    __syncthreads();                                              // bar 7

    // Phase E: out[d] = sum_j p_j * v[sel_j][d]; half-warp per key, float4.
    const float* vbase = v + (size_t)bh * SQ * DQ;
    float4 acc = make_float4(0.0f, 0.0f, 0.0f, 0.0f);
    jj = 2 * wid + half;
    for (; jj + 16 < KP; jj += 32) {
        float p0 = score[jj], p1 = score[jj + 16];
        float4 va = reinterpret_cast<const float4*>(vbase + (size_t)sel[jj] * DQ)[hl];
        float4 vb = reinterpret_cast<const float4*>(vbase + (size_t)sel[jj + 16] * DQ)[hl];
        acc.x += p0 * va.x + p1 * vb.x;
        acc.y += p0 * va.y + p1 * vb.y;
        acc.z += p0 * va.z + p1 * vb.z;
        acc.w += p0 * va.w + p1 * vb.w;
    }
    for (; jj < KP; jj += 16) {
        float p0 = score[jj];
        float4 va = reinterpret_cast<const float4*>(vbase + (size_t)sel[jj] * DQ)[hl];
        acc.x += p0 * va.x;
        acc.y += p0 * va.y;
        acc.z += p0 * va.z;
        acc.w += p0 * va.w;
    }
    oacc[wid * 2 + half][hl] = acc;
    __syncthreads();                                              // bar 8
    if (tid < DQ) {
        const float* of = reinterpret_cast<const float*>(oacc);  // [16][64]
        float r = 0.0f;
        #pragma unroll
        for (int s = 0; s < 16; s++) r += of[s * 64 + tid];
        out[(size_t)row * DQ + tid] = r;
    }
}

extern "C" void kernel_launch(void* const* d_in, const int* in_sizes, int n_in,
                              void* d_out, int out_size) {
    const float* q    = (const float*)d_in[0];
    const float* k    = (const float*)d_in[1];
    const float* v    = (const float*)d_in[2];
    const float* mask = (const float*)d_in[3];
    float* out = (float*)d_out;

    pack_kernel<<<ROWS / 8, 256>>>(k);          // 8 warps/block, 3072 blocks
    attn_kernel<<<ROWS, 256>>>(q, k, v, mask, out);
}

// round 16
// speedup vs baseline: 1.2484x; 1.0493x over previous
#include <cuda_runtime.h>

#define BQ 2
#define HQ 12
#define SQ 1024
#define DQ 64
#define KP 102            // max(1, int(1024 * 0.1))
#define ROWS (BQ * HQ * SQ)   // 24576 query rows

// Scratch (allocation-free contract): packed k sign bits, one u64 per key row.
__device__ unsigned long long g_kbits[ROWS];

// ---------------------------------------------------------------------------
// Kernel 1: pack sign bits of k rows into uint64 (warp per row).
// sign-dot = 64 - 2*popc(xor); score desc == popcount asc; ties -> lower idx.
// ---------------------------------------------------------------------------
__global__ void pack_kernel(const float* __restrict__ k) {
    int warp = (blockIdx.x * blockDim.x + threadIdx.x) >> 5;
    int lane = threadIdx.x & 31;
    if (warp >= ROWS) return;
    const float* kr = k + (size_t)warp * DQ;
    unsigned klo = __ballot_sync(0xffffffffu, kr[lane] > 0.0f);
    unsigned khi = __ballot_sync(0xffffffffu, kr[lane + 32] > 0.0f);
    if (lane == 0)
        g_kbits[warp] = ((unsigned long long)khi << 32) | klo;
}

// ---------------------------------------------------------------------------
// Kernel 2: one CTA (256 threads) per query row. Atomic-free, 8 barriers.
//   A: popcounts (registers, MLP-4) + match-aggregated per-warp hist (smem)
//   B1: warp-0 parallel reduce+scan+ballot cutoff
//   B2/B3: dual ballots; every warp redundantly scans word prefixes
//   C: precise scores, 8-lane group per key (4 keys/warp, 3 shfl steps total)
//   D: softmax (warp 0)
//   E: weighted v accumulation, half-warp per key, float4, MLP=2
// ---------------------------------------------------------------------------
__global__ __launch_bounds__(256) void attn_kernel(
    const float* __restrict__ q, const float* __restrict__ k,
    const float* __restrict__ v, const float* __restrict__ mask,
    float* __restrict__ out)
{
    int row = blockIdx.x;          // ((b*H + h) * S + s)
    int bh  = row >> 10;           // b*H + h
    int b   = bh / HQ;
    const unsigned long long* kb = g_kbits + (size_t)bh * SQ;
    const float* mrow = mask + (size_t)b * SQ;

    __shared__ int   histw[8][65];          // per-warp histogram slices
    __shared__ int   sel[KP];
    __shared__ __align__(16) float qs[DQ];
    __shared__ float score[KP];
    __shared__ float smask[SQ];             // mask row, coalesced preload
    __shared__ unsigned flagl[32], flage[32];
    __shared__ int   cstar_s, nless_s, remaining_s;
    __shared__ __align__(16) float4 oacc[16][16];  // [slot][hl]

    int tid  = threadIdx.x;
    int lane = tid & 31;
    int wid  = tid >> 5;
    int half = lane >> 4;          // Phase E: which key of the warp's pair
    int hl   = lane & 15;          // Phase E: lane within the 16-lane half
    int g    = lane >> 3;          // Phase C: 4 groups of 8 lanes
    int gl   = lane & 7;           // Phase C: lane within group

    // init + coalesced preloads
    for (int i = tid; i < 8 * 65; i += 256) ((int*)histw)[i] = 0;
    if (tid < DQ) qs[tid] = q[(size_t)row * DQ + tid];
    #pragma unroll
    for (int c = 0; c < 4; c++) smask[c * 256 + tid] = mrow[c * 256 + tid];
    __syncthreads();                                              // bar 1

    // q sign bits: every warp computes redundantly from smem (no barrier)
    unsigned qlo = __ballot_sync(0xffffffffu, qs[lane] > 0.0f);
    unsigned qhi = __ballot_sync(0xffffffffu, qs[lane + 32] > 0.0f);
    unsigned long long qbits = ((unsigned long long)qhi << 32) | qlo;

    // Phase A: popcounts (4 loads in flight), non-atomic per-warp hist.
    int p[4];
    #pragma unroll
    for (int c = 0; c < 4; c++)
        p[c] = __popcll(qbits ^ kb[c * 256 + tid]);
    #pragma unroll
    for (int c = 0; c < 4; c++) {
        unsigned mm = __match_any_sync(0xffffffffu, p[c]);
        if ((mm & ((1u << lane) - 1u)) == 0)     // lowest lane of match group
            histw[wid][p[c]] += __popc(mm);
        __syncwarp();  // order iteration c's STS before c+1's LDS
    }
    __syncthreads();                                              // bar 2

    // Phase B1: warp 0 fused reduce + inclusive scan + cutoff (bins 2l,2l+1)
    if (wid == 0) {
        int x0 = 0, x1 = 0;
        #pragma unroll
        for (int w = 0; w < 8; w++) {
            x0 += histw[w][2 * lane];
            x1 += histw[w][2 * lane + 1];
        }
        int pair = x0 + x1;
        int incl = pair;
        #pragma unroll
        for (int o = 1; o < 32; o <<= 1) {
            int t = __shfl_up_sync(0xffffffffu, incl, o);
            if (lane >= o) incl += t;
        }
        int excl = incl - pair;          // cum before bin 2*lane
        unsigned bal = __ballot_sync(0xffffffffu, incl >= KP);
        if (bal) {
            int lstar = __ffs(bal) - 1;
            if (lane == lstar) {
                int cst, nls;
                if (excl + x0 >= KP) { cst = 2 * lane;     nls = excl; }
                else                 { cst = 2 * lane + 1; nls = excl + x0; }
                cstar_s = cst; nless_s = nls; remaining_s = KP - nls;
            }
        } else if (lane == 31) {         // pathological: cutoff in bin 64
            cstar_s = 64; nless_s = incl; remaining_s = KP - incl;
        }
    }
    __syncthreads();                                              // bar 3
    int cstar = cstar_s, nless = nless_s, remaining = remaining_s;

    // Phase B2: dual packed flags (lt / eq) in key-index order
    #pragma unroll
    for (int c = 0; c < 4; c++) {
        unsigned blt = __ballot_sync(0xffffffffu, p[c] <  cstar);
        unsigned beq = __ballot_sync(0xffffffffu, p[c] == cstar);
        if (lane == 0) { flagl[c * 8 + wid] = blt; flage[c * 8 + wid] = beq; }
    }
    __syncthreads();                                              // bar 4

    // Every warp redundantly scans the 32 flag words (identical results).
    int cl = __popc(flagl[lane]);
    int ce = __popc(flage[lane]);
    int sl = cl, se = ce;
    #pragma unroll
    for (int o = 1; o < 32; o <<= 1) {
        int tl = __shfl_up_sync(0xffffffffu, sl, o);
        int te = __shfl_up_sync(0xffffffffu, se, o);
        if (lane >= o) { sl += tl; se += te; }
    }
    int el = sl - cl, ee = se - ce;      // exclusive prefix of word `lane`

    // Phase B3: atomic-free emit (JAX lower-index tie break for the eq bin)
    #pragma unroll
    for (int c = 0; c < 4; c++) {
        int t = c * 256 + tid;
        int w = c * 8 + wid;
        int basel = __shfl_sync(0xffffffffu, el, w);
        int basee = __shfl_sync(0xffffffffu, ee, w);
        if (p[c] < cstar) {
            sel[basel + __popc(flagl[w] & ((1u << lane) - 1u))] = t;
        } else if (p[c] == cstar) {
            int rank = basee + __popc(flage[w] & ((1u << lane) - 1u));
            if (rank < remaining) sel[nless + rank] = t;
        }
    }
    __syncthreads();                                              // bar 5

    // Phase C: precise scores. 8-lane group per key; 4 keys per warp-iter.
    // Lane gl holds dims [4gl,4gl+4) and [32+4gl,32+4gl+4): each LDG.128
    // instr touches exactly one 128B line per key (2 wavefronts/key total).
    // One 3-step shfl reduce covers all 4 keys at once.
    const float* kbase = k + (size_t)bh * SQ * DQ;
    float4 qa = reinterpret_cast<const float4*>(qs)[gl];
    float4 qb = reinterpret_cast<const float4*>(qs)[8 + gl];
    for (int base = 4 * wid; base < KP; base += 32) {
        int jj = base + g;
        bool valid = (jj < KP);
        int idx = sel[valid ? jj : 0];
        const float4* kr = reinterpret_cast<const float4*>(kbase + (size_t)idx * DQ);
        float4 ka  = kr[gl];
        float4 kb4 = kr[8 + gl];
        float pp = qa.x * ka.x  + qa.y * ka.y  + qa.z * ka.z  + qa.w * ka.w
                 + qb.x * kb4.x + qb.y * kb4.y + qb.z * kb4.z + qb.w * kb4.w;
        pp += __shfl_xor_sync(0xffffffffu, pp, 1);
        pp += __shfl_xor_sync(0xffffffffu, pp, 2);
        pp += __shfl_xor_sync(0xffffffffu, pp, 4);
        if (gl == 0 && valid)
            score[jj] = pp * 0.125f + smask[idx];
    }
    __syncthreads();                                              // bar 6

    // Phase D: softmax over 102 (warp 0)
    if (wid == 0) {
        float m = -1e30f;
        #pragma unroll
        for (int c = 0; c < 4; c++) {
            int j = c * 32 + lane;
            if (j < KP) m = fmaxf(m, score[j]);
        }
        #pragma unroll
        for (int o = 16; o; o >>= 1)
            m = fmaxf(m, __shfl_xor_sync(0xffffffffu, m, o));
        float s = 0.0f;
        float e[4];
        #pragma unroll
        for (int c = 0; c < 4; c++) {
            int j = c * 32 + lane;
            e[c] = (j < KP) ? __expf(score[j] - m) : 0.0f;
            s += e[c];
        }
        #pragma unroll
        for (int o = 16; o; o >>= 1)
            s += __shfl_xor_sync(0xffffffffu, s, o);
        float inv = 1.0f / s;
        #pragma unroll
        for (int c = 0; c < 4; c++) {
            int j = c * 32 + lane;
            if (j < KP) score[j] = e[c] * inv;
        }
    }
    __syncthreads();                                              // bar 7

    // Phase E: out[d] = sum_j p_j * v[sel_j][d]; half-warp per key, float4.
    const float* vbase = v + (size_t)bh * SQ * DQ;
    float4 acc = make_float4(0.0f, 0.0f, 0.0f, 0.0f);
    int jj = 2 * wid + half;
    for (; jj + 16 < KP; jj += 32) {
        float p0 = score[jj], p1 = score[jj + 16];
        float4 va = reinterpret_cast<const float4*>(vbase + (size_t)sel[jj] * DQ)[hl];
        float4 vb = reinterpret_cast<const float4*>(vbase + (size_t)sel[jj + 16] * DQ)[hl];
        acc.x += p0 * va.x + p1 * vb.x;
        acc.y += p0 * va.y + p1 * vb.y;
        acc.z += p0 * va.z + p1 * vb.z;
        acc.w += p0 * va.w + p1 * vb.w;
    }
    for (; jj < KP; jj += 16) {
        float p0 = score[jj];
        float4 va = reinterpret_cast<const float4*>(vbase + (size_t)sel[jj] * DQ)[hl];
        acc.x += p0 * va.x;
        acc.y += p0 * va.y;
        acc.z += p0 * va.z;
        acc.w += p0 * va.w;
    }
    oacc[wid * 2 + half][hl] = acc;
    __syncthreads();                                              // bar 8
    if (tid < DQ) {
        const float* of = reinterpret_cast<const float*>(oacc);  // [16][64]
        float r = 0.0f;
        #pragma unroll
        for (int s = 0; s < 16; s++) r += of[s * 64 + tid];
        out[(size_t)row * DQ + tid] = r;
    }
}

extern "C" void kernel_launch(void* const* d_in, const int* in_sizes, int n_in,
                              void* d_out, int out_size) {
    const float* q    = (const float*)d_in[0];
    const float* k    = (const float*)d_in[1];
    const float* v    = (const float*)d_in[2];
    const float* mask = (const float*)d_in[3];
    float* out = (float*)d_out;

    pack_kernel<<<ROWS / 8, 256>>>(k);          // 8 warps/block, 3072 blocks
    attn_kernel<<<ROWS, 256>>>(q, k, v, mask, out);
}